// round 4
// baseline (speedup 1.0000x reference)
#include <cuda_runtime.h>
#include <math.h>

#define N_NODES 100000
#define E_EDGES 1600000
#define E2      (E_EDGES + N_NODES)   // 1,700,000 (edges + self loops)
#define IN_C    128
#define HID     64
#define HEADS   4
#define HH      (HEADS * HID)         // 256
#define OUT_C   2
#define NEG_SLOPE 0.2f
#define SCAN_T  1024

struct Edge { int src; float norm; };

// ---------------- scratch (static device globals) --------------------------
__device__ __align__(16) int   g_degi[N_NODES];
__device__ __align__(16) int   g_cnt[N_NODES];
__device__ __align__(16) int   g_rowptr[N_NODES + 1];
__device__ __align__(16) float g_dinv[N_NODES];
__device__ __align__(16) Edge  g_csr[E2];
__device__ __align__(16) float g_xw1[(size_t)N_NODES * HID];
__device__ __align__(16) float g_h0 [(size_t)N_NODES * HID];
__device__ __align__(16) float g_xw2[(size_t)N_NODES * HH];
__device__ __align__(16) float g_as [(size_t)N_NODES * HEADS];
__device__ __align__(16) float g_ad [(size_t)N_NODES * HEADS];
__device__ __align__(16) float g_mx[8];        // [0..3]=max a_s per head, [4..7]=max a_d
__device__ __align__(16) float g_hw3[(size_t)N_NODES * OUT_C];

__device__ __forceinline__ float lrelu(float x) { return x > 0.0f ? x : NEG_SLOPE * x; }

__device__ __forceinline__ void atomicMaxFloat(float* addr, float value) {
    if (value >= 0.0f) atomicMax((int*)addr, __float_as_int(value));
    else               atomicMin((unsigned int*)addr, __float_as_uint(value));
}

// ---------------- CSR build -------------------------------------------------
__global__ void k_init() {
    int i = blockIdx.x * blockDim.x + threadIdx.x;
    if (i < N_NODES) { g_degi[i] = 0; g_cnt[i] = 0; }
    if (i < 8) g_mx[i] = -3.402823466e38f;
}

__global__ void k_edges(const int* __restrict__ ei) {
    int e = blockIdx.x * blockDim.x + threadIdx.x;
    if (e >= E2) return;
    int d = (e < E_EDGES) ? ei[E_EDGES + e] : (e - E_EDGES);
    atomicAdd(&g_degi[d], 1);
}

// single-block exclusive scan of degrees -> rowptr; also dinv
__global__ void k_scan() {
    __shared__ int part[SCAN_T];
    const int CH = (N_NODES + SCAN_T - 1) / SCAN_T;   // 98
    int t = threadIdx.x;
    int base = t * CH;
    int hi = min(base + CH, N_NODES);
    int sum = 0;
    for (int i = base; i < hi; i++) sum += g_degi[i];
    part[t] = sum;
    __syncthreads();
    for (int off = 1; off < SCAN_T; off <<= 1) {
        int v = (t >= off) ? part[t - off] : 0;
        __syncthreads();
        part[t] += v;
        __syncthreads();
    }
    int run = (t == 0) ? 0 : part[t - 1];
    for (int i = base; i < hi; i++) {
        g_rowptr[i] = run;
        int dg = g_degi[i];
        g_dinv[i] = dg > 0 ? rsqrtf((float)dg) : 0.0f;
        run += dg;
    }
    if (t == SCAN_T - 1) g_rowptr[N_NODES] = run;
}

__global__ void k_fill(const int* __restrict__ ei) {
    int e = blockIdx.x * blockDim.x + threadIdx.x;
    if (e >= E2) return;
    int s, d;
    if (e < E_EDGES) { s = ei[e]; d = ei[E_EDGES + e]; }
    else             { s = e - E_EDGES; d = s; }
    int pos = g_rowptr[d] + atomicAdd(&g_cnt[d], 1);
    Edge ed; ed.src = s; ed.norm = g_dinv[s] * g_dinv[d];
    g_csr[pos] = ed;                               // single 8B store
}

// ---------------- GEMM 1: xw1 = x @ W1  [N,128]x[128,64] -------------------
__global__ void k_gemm1(const float* __restrict__ x, const float* __restrict__ W1) {
    __shared__ __align__(16) float As[16][IN_C + 4];
    __shared__ __align__(16) float Bs[IN_C][HID];
    int tid = threadIdx.x;                       // 256 threads
    for (int i = tid; i < IN_C * HID / 4; i += 256)
        ((float4*)&Bs[0][0])[i] = ((const float4*)W1)[i];
    int row0 = blockIdx.x * 16;
    for (int i = tid; i < 16 * IN_C / 4; i += 256) {
        int r = i / (IN_C / 4), k4 = i % (IN_C / 4);
        *(float4*)&As[r][k4 * 4] =
            *(const float4*)&x[(size_t)(row0 + r) * IN_C + k4 * 4];
    }
    __syncthreads();
    int r = tid >> 4, cg = tid & 15;             // 4 cols per thread
    float a0 = 0, a1 = 0, a2 = 0, a3 = 0;
    #pragma unroll 8
    for (int k = 0; k < IN_C; k++) {
        float a = As[r][k];
        float4 b = *(const float4*)&Bs[k][cg * 4];
        a0 += a * b.x; a1 += a * b.y; a2 += a * b.z; a3 += a * b.w;
    }
    float4 o; o.x = a0; o.y = a1; o.z = a2; o.w = a3;
    *(float4*)&g_xw1[(size_t)(row0 + r) * HID + cg * 4] = o;
}

// ---------------- GCN-1 gather: h0[d] = relu(sum xw1[s]*norm + b1) ---------
__global__ void k_gcn1(const float* __restrict__ b1) {
    int warp = (blockIdx.x * blockDim.x + threadIdx.x) >> 5;
    int lane = threadIdx.x & 31;
    if (warp >= N_NODES) return;
    int r0 = g_rowptr[warp], r1 = g_rowptr[warp + 1];
    float acc0 = 0.0f, acc1 = 0.0f;
    for (int e = r0; e < r1; e++) {
        Edge ed = g_csr[e];                        // 8B broadcast
        float2 v = *(const float2*)&g_xw1[(size_t)ed.src * HID + lane * 2];
        acc0 += v.x * ed.norm; acc1 += v.y * ed.norm;
    }
    float2 o;
    o.x = fmaxf(acc0 + __ldg(&b1[lane * 2]),     0.0f);
    o.y = fmaxf(acc1 + __ldg(&b1[lane * 2 + 1]), 0.0f);
    *(float2*)&g_h0[(size_t)warp * HID + lane * 2] = o;
}

// ---------------- GEMM 2: xw2 = h0 @ W2 (+ attention dots) -----------------
__global__ void k_gemm2(const float* __restrict__ W2,
                        const float* __restrict__ attS,
                        const float* __restrict__ attD) {
    __shared__ __align__(16) float As[16][HID + 4];
    __shared__ __align__(16) float Bs[HID][128];
    __shared__ float aS[2][HID], aD[2][HID];
    int tid = threadIdx.x;                       // 256
    int row0 = blockIdx.x * 16;
    for (int i = tid; i < 16 * HID / 4; i += 256) {
        int r = i / (HID / 4), k4 = i % (HID / 4);
        *(float4*)&As[r][k4 * 4] =
            *(const float4*)&g_h0[(size_t)(row0 + r) * HID + k4 * 4];
    }
    int r = tid >> 4, cg = tid & 15;             // 8 cols per thread per half
    for (int half = 0; half < 2; half++) {
        __syncthreads();
        for (int i = tid; i < HID * 128 / 4; i += 256) {
            int k = i / 32, c4 = i % 32;
            *(float4*)&Bs[k][c4 * 4] =
                *(const float4*)&W2[(size_t)k * HH + half * 128 + c4 * 4];
        }
        if (tid < 128) {
            aS[tid >> 6][tid & 63] = attS[half * 128 + tid];
            aD[tid >> 6][tid & 63] = attD[half * 128 + tid];
        }
        __syncthreads();
        float acc[8];
        #pragma unroll
        for (int j = 0; j < 8; j++) acc[j] = 0.0f;
        #pragma unroll 8
        for (int k = 0; k < HID; k++) {
            float a = As[r][k];
            float4 b0 = *(const float4*)&Bs[k][cg * 8];
            float4 b1 = *(const float4*)&Bs[k][cg * 8 + 4];
            acc[0] += a * b0.x; acc[1] += a * b0.y; acc[2] += a * b0.z; acc[3] += a * b0.w;
            acc[4] += a * b1.x; acc[5] += a * b1.y; acc[6] += a * b1.z; acc[7] += a * b1.w;
        }
        int colbase = half * 128 + cg * 8;
        float4 o0; o0.x = acc[0]; o0.y = acc[1]; o0.z = acc[2]; o0.w = acc[3];
        float4 o1; o1.x = acc[4]; o1.y = acc[5]; o1.z = acc[6]; o1.w = acc[7];
        size_t base = (size_t)(row0 + r) * HH + colbase;
        *(float4*)&g_xw2[base]     = o0;
        *(float4*)&g_xw2[base + 4] = o1;
        int hloc = cg >> 3;
        int off  = (cg & 7) * 8;
        float ps = 0.0f, pd = 0.0f;
        #pragma unroll
        for (int j = 0; j < 8; j++) {
            ps += acc[j] * aS[hloc][off + j];
            pd += acc[j] * aD[hloc][off + j];
        }
        #pragma unroll
        for (int o = 4; o >= 1; o >>= 1) {
            ps += __shfl_down_sync(0xffffffffu, ps, o);
            pd += __shfl_down_sync(0xffffffffu, pd, o);
        }
        if ((cg & 7) == 0) {
            int head = half * 2 + hloc;
            g_as[(size_t)(row0 + r) * HEADS + head] = ps;
            g_ad[(size_t)(row0 + r) * HEADS + head] = pd;
        }
    }
}

// ---------------- global per-head max of a_s / a_d -------------------------
__global__ void k_maxred() {
    int i = blockIdx.x * blockDim.x + threadIdx.x;
    int lane = threadIdx.x & 31;
    float4 a = make_float4(-3.4e38f, -3.4e38f, -3.4e38f, -3.4e38f);
    float4 d = a;
    if (i < N_NODES) {
        a = *(const float4*)&g_as[(size_t)i * HEADS];
        d = *(const float4*)&g_ad[(size_t)i * HEADS];
    }
    #pragma unroll
    for (int o = 16; o >= 1; o >>= 1) {
        a.x = fmaxf(a.x, __shfl_xor_sync(0xffffffffu, a.x, o));
        a.y = fmaxf(a.y, __shfl_xor_sync(0xffffffffu, a.y, o));
        a.z = fmaxf(a.z, __shfl_xor_sync(0xffffffffu, a.z, o));
        a.w = fmaxf(a.w, __shfl_xor_sync(0xffffffffu, a.w, o));
        d.x = fmaxf(d.x, __shfl_xor_sync(0xffffffffu, d.x, o));
        d.y = fmaxf(d.y, __shfl_xor_sync(0xffffffffu, d.y, o));
        d.z = fmaxf(d.z, __shfl_xor_sync(0xffffffffu, d.z, o));
        d.w = fmaxf(d.w, __shfl_xor_sync(0xffffffffu, d.w, o));
    }
    if (lane == 0) {
        atomicMaxFloat(&g_mx[0], a.x); atomicMaxFloat(&g_mx[1], a.y);
        atomicMaxFloat(&g_mx[2], a.z); atomicMaxFloat(&g_mx[3], a.w);
        atomicMaxFloat(&g_mx[4], d.x); atomicMaxFloat(&g_mx[5], d.y);
        atomicMaxFloat(&g_mx[6], d.z); atomicMaxFloat(&g_mx[7], d.w);
    }
}

// ---------------- fused GAT: single edge pass + bias + ELU + GEMM3 ---------
// Shift-invariant softmax: subtract C_h = lrelu(max a_s + max a_d) (global
// per-head upper bound) instead of per-dst max — mathematically identical.
__global__ void __launch_bounds__(256) k_gat(const float* __restrict__ b2,
                                             const float* __restrict__ W3) {
    __shared__ float sW3[HH * 2];
    __shared__ float sb2[HH];
    __shared__ float sC[HEADS];
    int tid = threadIdx.x;
    sW3[tid * 2]     = W3[tid * 2];
    sW3[tid * 2 + 1] = W3[tid * 2 + 1];
    sb2[tid]         = b2[tid];
    if (tid < HEADS) sC[tid] = lrelu(g_mx[tid] + g_mx[tid + 4]);
    __syncthreads();

    int warp = blockIdx.x * 8 + (tid >> 5);
    int lane = tid & 31;
    if (warp >= N_NODES) return;
    int r0 = g_rowptr[warp], r1 = g_rowptr[warp + 1];

    int head = lane >> 3;                        // 8 lanes per head
    int col  = lane * 8;
    float adh = g_ad[(size_t)warp * HEADS + head];
    float Ch  = sC[head];

    float acc[8];
    #pragma unroll
    for (int j = 0; j < 8; j++) acc[j] = 0.0f;
    float den = 0.0f;

    for (int e = r0; e < r1; e++) {
        int s = g_csr[e].src;                    // broadcast
        float ash = g_as[(size_t)s * HEADS + head];   // 16B sector broadcast
        float w = __expf(lrelu(ash + adh) - Ch);
        den += w;
        const float4* p = (const float4*)&g_xw2[(size_t)s * HH + col];
        float4 v0 = p[0], v1 = p[1];
        acc[0] += v0.x * w; acc[1] += v0.y * w;
        acc[2] += v0.z * w; acc[3] += v0.w * w;
        acc[4] += v1.x * w; acc[5] += v1.y * w;
        acc[6] += v1.z * w; acc[7] += v1.w * w;
    }
    float inv = 1.0f / den;                      // den>0 (self-loop)

    // epilogue: normalize, +b2, ELU, dot with W3 columns (fused gemm3)
    float a0 = 0.0f, a1 = 0.0f;
    #pragma unroll
    for (int j = 0; j < 8; j++) {
        int c = col + j;
        float v = acc[j] * inv + sb2[c];
        v = v > 0.0f ? v : expm1f(v);
        a0 += v * sW3[c * 2];
        a1 += v * sW3[c * 2 + 1];
    }
    #pragma unroll
    for (int o = 16; o >= 1; o >>= 1) {
        a0 += __shfl_xor_sync(0xffffffffu, a0, o);
        a1 += __shfl_xor_sync(0xffffffffu, a1, o);
    }
    if (lane == 0) {
        g_hw3[(size_t)warp * 2]     = a0;
        g_hw3[(size_t)warp * 2 + 1] = a1;
    }
}

// ---------------- GCN-2 gather: out[d] = sum hw3[s]*norm + b3 --------------
__global__ void k_gcn2(const float* __restrict__ b3, float* __restrict__ out) {
    int warp = (blockIdx.x * blockDim.x + threadIdx.x) >> 5;
    int lane = threadIdx.x & 31;
    if (warp >= N_NODES) return;
    int r0 = g_rowptr[warp], r1 = g_rowptr[warp + 1];
    float acc0 = 0.0f, acc1 = 0.0f;
    for (int e = r0 + lane; e < r1; e += 32) {
        Edge ed = g_csr[e];
        float2 v = *(const float2*)&g_hw3[(size_t)ed.src * 2];
        acc0 += v.x * ed.norm; acc1 += v.y * ed.norm;
    }
    #pragma unroll
    for (int o = 16; o >= 1; o >>= 1) {
        acc0 += __shfl_xor_sync(0xffffffffu, acc0, o);
        acc1 += __shfl_xor_sync(0xffffffffu, acc1, o);
    }
    if (lane == 0) {
        out[(size_t)warp * 2]     = acc0 + __ldg(&b3[0]);
        out[(size_t)warp * 2 + 1] = acc1 + __ldg(&b3[1]);
    }
}

// ---------------- launch -----------------------------------------------------
extern "C" void kernel_launch(void* const* d_in, const int* in_sizes, int n_in,
                              void* d_out, int out_size) {
    const float* x    = (const float*)d_in[0];
    const int*   ei   = (const int*)d_in[1];      // int32
    const float* W1   = (const float*)d_in[2];
    const float* b1   = (const float*)d_in[3];
    const float* W2   = (const float*)d_in[4];
    const float* attS = (const float*)d_in[5];
    const float* attD = (const float*)d_in[6];
    const float* b2   = (const float*)d_in[7];
    const float* W3   = (const float*)d_in[8];
    const float* b3   = (const float*)d_in[9];
    float* out = (float*)d_out;

    const int T = 256;
    k_init  <<<(N_NODES + T - 1) / T, T>>>();
    k_edges <<<(E2 + T - 1) / T, T>>>(ei);
    k_scan  <<<1, SCAN_T>>>();
    k_fill  <<<(E2 + T - 1) / T, T>>>(ei);
    k_gemm1 <<<N_NODES / 16, T>>>(x, W1);
    k_gcn1  <<<(N_NODES * 32 + T - 1) / T, T>>>(b1);
    k_gemm2 <<<N_NODES / 16, T>>>(W2, attS, attD);
    k_maxred<<<(N_NODES + T - 1) / T, T>>>();
    k_gat   <<<(N_NODES + 7) / 8, T>>>(b2, W3);
    k_gcn2  <<<(N_NODES * 32 + T - 1) / T, T>>>(b3, out);
}

// round 5
// speedup vs baseline: 1.0132x; 1.0132x over previous
#include <cuda_runtime.h>
#include <math.h>

#define N_NODES 100000
#define E_EDGES 1600000
#define E2      (E_EDGES + N_NODES)   // 1,700,000 (edges + self loops)
#define IN_C    128
#define HID     64
#define HEADS   4
#define HH      (HEADS * HID)         // 256
#define OUT_C   2
#define NEG_SLOPE 0.2f
#define SCAN_T  1024

struct Edge { int src; float norm; };

// ---------------- scratch (static device globals) --------------------------
__device__ __align__(16) int   g_degi[N_NODES];
__device__ __align__(16) int   g_cnt[N_NODES];
__device__ __align__(16) int   g_rowptr[N_NODES + 1];
__device__ __align__(16) float g_dinv[N_NODES];
__device__ __align__(16) Edge  g_csr[E2];
__device__ __align__(16) float g_xw1[(size_t)N_NODES * HID];
__device__ __align__(16) float g_h0 [(size_t)N_NODES * HID];
__device__ __align__(16) float g_xw2[(size_t)N_NODES * HH];
__device__ __align__(16) float g_as [(size_t)N_NODES * HEADS];
__device__ __align__(16) float g_ad [(size_t)N_NODES * HEADS];
__device__ __align__(16) float g_mx[8];        // [0..3]=max a_s per head, [4..7]=max a_d
__device__ __align__(16) float g_hw3[(size_t)N_NODES * OUT_C];

__device__ __forceinline__ float lrelu(float x) { return x > 0.0f ? x : NEG_SLOPE * x; }

__device__ __forceinline__ void atomicMaxFloat(float* addr, float value) {
    if (value >= 0.0f) atomicMax((int*)addr, __float_as_int(value));
    else               atomicMin((unsigned int*)addr, __float_as_uint(value));
}

// ---------------- CSR build -------------------------------------------------
__global__ void k_init() {
    int i = blockIdx.x * blockDim.x + threadIdx.x;
    if (i < N_NODES) { g_degi[i] = 0; g_cnt[i] = 0; }
    if (i < 8) g_mx[i] = -3.402823466e38f;
}

__global__ void k_edges(const int* __restrict__ ei) {
    int e = blockIdx.x * blockDim.x + threadIdx.x;
    if (e >= E2) return;
    int d = (e < E_EDGES) ? ei[E_EDGES + e] : (e - E_EDGES);
    atomicAdd(&g_degi[d], 1);
}

// single-block exclusive scan of degrees -> rowptr; also dinv
__global__ void k_scan() {
    __shared__ int part[SCAN_T];
    const int CH = (N_NODES + SCAN_T - 1) / SCAN_T;   // 98
    int t = threadIdx.x;
    int base = t * CH;
    int hi = min(base + CH, N_NODES);
    int sum = 0;
    for (int i = base; i < hi; i++) sum += g_degi[i];
    part[t] = sum;
    __syncthreads();
    for (int off = 1; off < SCAN_T; off <<= 1) {
        int v = (t >= off) ? part[t - off] : 0;
        __syncthreads();
        part[t] += v;
        __syncthreads();
    }
    int run = (t == 0) ? 0 : part[t - 1];
    for (int i = base; i < hi; i++) {
        g_rowptr[i] = run;
        int dg = g_degi[i];
        g_dinv[i] = dg > 0 ? rsqrtf((float)dg) : 0.0f;
        run += dg;
    }
    if (t == SCAN_T - 1) g_rowptr[N_NODES] = run;
}

__global__ void k_fill(const int* __restrict__ ei) {
    int e = blockIdx.x * blockDim.x + threadIdx.x;
    if (e >= E2) return;
    int s, d;
    if (e < E_EDGES) { s = ei[e]; d = ei[E_EDGES + e]; }
    else             { s = e - E_EDGES; d = s; }
    int pos = g_rowptr[d] + atomicAdd(&g_cnt[d], 1);
    Edge ed; ed.src = s; ed.norm = g_dinv[s] * g_dinv[d];
    g_csr[pos] = ed;                               // single 8B store
}

// ---------------- GEMM 1: xw1 = x @ W1  [N,128]x[128,64] -------------------
__global__ void k_gemm1(const float* __restrict__ x, const float* __restrict__ W1) {
    __shared__ __align__(16) float As[16][IN_C + 4];
    __shared__ __align__(16) float Bs[IN_C][HID];
    int tid = threadIdx.x;                       // 256 threads
    for (int i = tid; i < IN_C * HID / 4; i += 256)
        ((float4*)&Bs[0][0])[i] = ((const float4*)W1)[i];
    int row0 = blockIdx.x * 16;
    for (int i = tid; i < 16 * IN_C / 4; i += 256) {
        int r = i / (IN_C / 4), k4 = i % (IN_C / 4);
        *(float4*)&As[r][k4 * 4] =
            *(const float4*)&x[(size_t)(row0 + r) * IN_C + k4 * 4];
    }
    __syncthreads();
    int r = tid >> 4, cg = tid & 15;             // 4 cols per thread
    float a0 = 0, a1 = 0, a2 = 0, a3 = 0;
    #pragma unroll 8
    for (int k = 0; k < IN_C; k++) {
        float a = As[r][k];
        float4 b = *(const float4*)&Bs[k][cg * 4];
        a0 += a * b.x; a1 += a * b.y; a2 += a * b.z; a3 += a * b.w;
    }
    float4 o; o.x = a0; o.y = a1; o.z = a2; o.w = a3;
    *(float4*)&g_xw1[(size_t)(row0 + r) * HID + cg * 4] = o;
}

// ---------------- GCN-1 gather: h0[d] = relu(sum xw1[s]*norm + b1) ---------
__global__ void k_gcn1(const float* __restrict__ b1) {
    int warp = (blockIdx.x * blockDim.x + threadIdx.x) >> 5;
    int lane = threadIdx.x & 31;
    if (warp >= N_NODES) return;
    int r0 = g_rowptr[warp], r1 = g_rowptr[warp + 1];
    float acc0 = 0.0f, acc1 = 0.0f;
    int off = lane * 2;
    int e = r0;
    for (; e + 4 <= r1; e += 4) {
        Edge e0 = g_csr[e], e1 = g_csr[e + 1], e2 = g_csr[e + 2], e3 = g_csr[e + 3];
        float2 v0 = *(const float2*)&g_xw1[(size_t)e0.src * HID + off];
        float2 v1 = *(const float2*)&g_xw1[(size_t)e1.src * HID + off];
        float2 v2 = *(const float2*)&g_xw1[(size_t)e2.src * HID + off];
        float2 v3 = *(const float2*)&g_xw1[(size_t)e3.src * HID + off];
        acc0 += v0.x * e0.norm + v1.x * e1.norm + v2.x * e2.norm + v3.x * e3.norm;
        acc1 += v0.y * e0.norm + v1.y * e1.norm + v2.y * e2.norm + v3.y * e3.norm;
    }
    for (; e < r1; e++) {
        Edge ed = g_csr[e];
        float2 v = *(const float2*)&g_xw1[(size_t)ed.src * HID + off];
        acc0 += v.x * ed.norm; acc1 += v.y * ed.norm;
    }
    float2 o;
    o.x = fmaxf(acc0 + __ldg(&b1[off]),     0.0f);
    o.y = fmaxf(acc1 + __ldg(&b1[off + 1]), 0.0f);
    *(float2*)&g_h0[(size_t)warp * HID + off] = o;
}

// ---------------- GEMM 2: xw2 = h0 @ W2 (+ attention dots) -----------------
__global__ void k_gemm2(const float* __restrict__ W2,
                        const float* __restrict__ attS,
                        const float* __restrict__ attD) {
    __shared__ __align__(16) float As[16][HID + 4];
    __shared__ __align__(16) float Bs[HID][128];
    __shared__ float aS[2][HID], aD[2][HID];
    int tid = threadIdx.x;                       // 256
    int row0 = blockIdx.x * 16;
    for (int i = tid; i < 16 * HID / 4; i += 256) {
        int r = i / (HID / 4), k4 = i % (HID / 4);
        *(float4*)&As[r][k4 * 4] =
            *(const float4*)&g_h0[(size_t)(row0 + r) * HID + k4 * 4];
    }
    int r = tid >> 4, cg = tid & 15;             // 8 cols per thread per half
    for (int half = 0; half < 2; half++) {
        __syncthreads();
        for (int i = tid; i < HID * 128 / 4; i += 256) {
            int k = i / 32, c4 = i % 32;
            *(float4*)&Bs[k][c4 * 4] =
                *(const float4*)&W2[(size_t)k * HH + half * 128 + c4 * 4];
        }
        if (tid < 128) {
            aS[tid >> 6][tid & 63] = attS[half * 128 + tid];
            aD[tid >> 6][tid & 63] = attD[half * 128 + tid];
        }
        __syncthreads();
        float acc[8];
        #pragma unroll
        for (int j = 0; j < 8; j++) acc[j] = 0.0f;
        #pragma unroll 8
        for (int k = 0; k < HID; k++) {
            float a = As[r][k];
            float4 b0 = *(const float4*)&Bs[k][cg * 8];
            float4 b1 = *(const float4*)&Bs[k][cg * 8 + 4];
            acc[0] += a * b0.x; acc[1] += a * b0.y; acc[2] += a * b0.z; acc[3] += a * b0.w;
            acc[4] += a * b1.x; acc[5] += a * b1.y; acc[6] += a * b1.z; acc[7] += a * b1.w;
        }
        int colbase = half * 128 + cg * 8;
        float4 o0; o0.x = acc[0]; o0.y = acc[1]; o0.z = acc[2]; o0.w = acc[3];
        float4 o1; o1.x = acc[4]; o1.y = acc[5]; o1.z = acc[6]; o1.w = acc[7];
        size_t base = (size_t)(row0 + r) * HH + colbase;
        *(float4*)&g_xw2[base]     = o0;
        *(float4*)&g_xw2[base + 4] = o1;
        int hloc = cg >> 3;
        int off  = (cg & 7) * 8;
        float ps = 0.0f, pd = 0.0f;
        #pragma unroll
        for (int j = 0; j < 8; j++) {
            ps += acc[j] * aS[hloc][off + j];
            pd += acc[j] * aD[hloc][off + j];
        }
        #pragma unroll
        for (int o = 4; o >= 1; o >>= 1) {
            ps += __shfl_down_sync(0xffffffffu, ps, o);
            pd += __shfl_down_sync(0xffffffffu, pd, o);
        }
        if ((cg & 7) == 0) {
            int head = half * 2 + hloc;
            g_as[(size_t)(row0 + r) * HEADS + head] = ps;
            g_ad[(size_t)(row0 + r) * HEADS + head] = pd;
        }
    }
}

// ---------------- global per-head max of a_s / a_d -------------------------
__global__ void k_maxred() {
    int i = blockIdx.x * blockDim.x + threadIdx.x;
    int lane = threadIdx.x & 31;
    float4 a = make_float4(-3.4e38f, -3.4e38f, -3.4e38f, -3.4e38f);
    float4 d = a;
    if (i < N_NODES) {
        a = *(const float4*)&g_as[(size_t)i * HEADS];
        d = *(const float4*)&g_ad[(size_t)i * HEADS];
    }
    #pragma unroll
    for (int o = 16; o >= 1; o >>= 1) {
        a.x = fmaxf(a.x, __shfl_xor_sync(0xffffffffu, a.x, o));
        a.y = fmaxf(a.y, __shfl_xor_sync(0xffffffffu, a.y, o));
        a.z = fmaxf(a.z, __shfl_xor_sync(0xffffffffu, a.z, o));
        a.w = fmaxf(a.w, __shfl_xor_sync(0xffffffffu, a.w, o));
        d.x = fmaxf(d.x, __shfl_xor_sync(0xffffffffu, d.x, o));
        d.y = fmaxf(d.y, __shfl_xor_sync(0xffffffffu, d.y, o));
        d.z = fmaxf(d.z, __shfl_xor_sync(0xffffffffu, d.z, o));
        d.w = fmaxf(d.w, __shfl_xor_sync(0xffffffffu, d.w, o));
    }
    if (lane == 0) {
        atomicMaxFloat(&g_mx[0], a.x); atomicMaxFloat(&g_mx[1], a.y);
        atomicMaxFloat(&g_mx[2], a.z); atomicMaxFloat(&g_mx[3], a.w);
        atomicMaxFloat(&g_mx[4], d.x); atomicMaxFloat(&g_mx[5], d.y);
        atomicMaxFloat(&g_mx[6], d.z); atomicMaxFloat(&g_mx[7], d.w);
    }
}

// ---------------- fused GAT: single edge pass + bias + ELU + GEMM3 ---------
// Shift-invariant softmax: subtract C_h = lrelu(max a_s + max a_d) (global
// per-head upper bound) — mathematically identical to per-dst max softmax.
// 4-edge unroll to batch the random loads (MLP ~12 vs ~3).
__global__ void __launch_bounds__(256) k_gat(const float* __restrict__ b2,
                                             const float* __restrict__ W3) {
    __shared__ float sW3[HH * 2];
    __shared__ float sb2[HH];
    __shared__ float sC[HEADS];
    int tid = threadIdx.x;
    sW3[tid * 2]     = W3[tid * 2];
    sW3[tid * 2 + 1] = W3[tid * 2 + 1];
    sb2[tid]         = b2[tid];
    if (tid < HEADS) sC[tid] = lrelu(g_mx[tid] + g_mx[tid + 4]);
    __syncthreads();

    int warp = blockIdx.x * 8 + (tid >> 5);
    int lane = tid & 31;
    if (warp >= N_NODES) return;
    int r0 = g_rowptr[warp], r1 = g_rowptr[warp + 1];

    int head = lane >> 3;                        // 8 lanes per head
    int col  = lane * 8;
    float adh = g_ad[(size_t)warp * HEADS + head];
    float Ch  = sC[head];

    float acc[8];
    #pragma unroll
    for (int j = 0; j < 8; j++) acc[j] = 0.0f;
    float den = 0.0f;

    int e = r0;
    for (; e + 4 <= r1; e += 4) {
        int s0 = g_csr[e].src,     s1 = g_csr[e + 1].src;
        int s2 = g_csr[e + 2].src, s3 = g_csr[e + 3].src;
        float as0 = g_as[(size_t)s0 * HEADS + head];
        float as1 = g_as[(size_t)s1 * HEADS + head];
        float as2 = g_as[(size_t)s2 * HEADS + head];
        float as3 = g_as[(size_t)s3 * HEADS + head];
        const float4* p0 = (const float4*)&g_xw2[(size_t)s0 * HH + col];
        const float4* p1 = (const float4*)&g_xw2[(size_t)s1 * HH + col];
        const float4* p2 = (const float4*)&g_xw2[(size_t)s2 * HH + col];
        const float4* p3 = (const float4*)&g_xw2[(size_t)s3 * HH + col];
        float4 v00 = p0[0], v01 = p0[1];
        float4 v10 = p1[0], v11 = p1[1];
        float4 v20 = p2[0], v21 = p2[1];
        float4 v30 = p3[0], v31 = p3[1];
        float w0 = __expf(lrelu(as0 + adh) - Ch);
        float w1 = __expf(lrelu(as1 + adh) - Ch);
        float w2 = __expf(lrelu(as2 + adh) - Ch);
        float w3 = __expf(lrelu(as3 + adh) - Ch);
        den += (w0 + w1) + (w2 + w3);
        acc[0] += v00.x * w0 + v10.x * w1 + v20.x * w2 + v30.x * w3;
        acc[1] += v00.y * w0 + v10.y * w1 + v20.y * w2 + v30.y * w3;
        acc[2] += v00.z * w0 + v10.z * w1 + v20.z * w2 + v30.z * w3;
        acc[3] += v00.w * w0 + v10.w * w1 + v20.w * w2 + v30.w * w3;
        acc[4] += v01.x * w0 + v11.x * w1 + v21.x * w2 + v31.x * w3;
        acc[5] += v01.y * w0 + v11.y * w1 + v21.y * w2 + v31.y * w3;
        acc[6] += v01.z * w0 + v11.z * w1 + v21.z * w2 + v31.z * w3;
        acc[7] += v01.w * w0 + v11.w * w1 + v21.w * w2 + v31.w * w3;
    }
    for (; e < r1; e++) {
        int s = g_csr[e].src;
        float ash = g_as[(size_t)s * HEADS + head];
        float w = __expf(lrelu(ash + adh) - Ch);
        den += w;
        const float4* p = (const float4*)&g_xw2[(size_t)s * HH + col];
        float4 v0 = p[0], v1 = p[1];
        acc[0] += v0.x * w; acc[1] += v0.y * w;
        acc[2] += v0.z * w; acc[3] += v0.w * w;
        acc[4] += v1.x * w; acc[5] += v1.y * w;
        acc[6] += v1.z * w; acc[7] += v1.w * w;
    }
    float inv = 1.0f / den;                      // den>0 (self-loop)

    // epilogue: normalize, +b2, ELU, dot with W3 columns (fused gemm3)
    float a0 = 0.0f, a1 = 0.0f;
    #pragma unroll
    for (int j = 0; j < 8; j++) {
        int c = col + j;
        float v = acc[j] * inv + sb2[c];
        v = v > 0.0f ? v : expm1f(v);
        a0 += v * sW3[c * 2];
        a1 += v * sW3[c * 2 + 1];
    }
    #pragma unroll
    for (int o = 16; o >= 1; o >>= 1) {
        a0 += __shfl_xor_sync(0xffffffffu, a0, o);
        a1 += __shfl_xor_sync(0xffffffffu, a1, o);
    }
    if (lane == 0) {
        g_hw3[(size_t)warp * 2]     = a0;
        g_hw3[(size_t)warp * 2 + 1] = a1;
    }
}

// ---------------- GCN-2 gather: out[d] = sum hw3[s]*norm + b3 --------------
__global__ void k_gcn2(const float* __restrict__ b3, float* __restrict__ out) {
    int warp = (blockIdx.x * blockDim.x + threadIdx.x) >> 5;
    int lane = threadIdx.x & 31;
    if (warp >= N_NODES) return;
    int r0 = g_rowptr[warp], r1 = g_rowptr[warp + 1];
    float acc0 = 0.0f, acc1 = 0.0f;
    for (int e = r0 + lane; e < r1; e += 32) {
        Edge ed = g_csr[e];
        float2 v = *(const float2*)&g_hw3[(size_t)ed.src * 2];
        acc0 += v.x * ed.norm; acc1 += v.y * ed.norm;
    }
    #pragma unroll
    for (int o = 16; o >= 1; o >>= 1) {
        acc0 += __shfl_xor_sync(0xffffffffu, acc0, o);
        acc1 += __shfl_xor_sync(0xffffffffu, acc1, o);
    }
    if (lane == 0) {
        out[(size_t)warp * 2]     = acc0 + __ldg(&b3[0]);
        out[(size_t)warp * 2 + 1] = acc1 + __ldg(&b3[1]);
    }
}

// ---------------- launch -----------------------------------------------------
extern "C" void kernel_launch(void* const* d_in, const int* in_sizes, int n_in,
                              void* d_out, int out_size) {
    const float* x    = (const float*)d_in[0];
    const int*   ei   = (const int*)d_in[1];      // int32
    const float* W1   = (const float*)d_in[2];
    const float* b1   = (const float*)d_in[3];
    const float* W2   = (const float*)d_in[4];
    const float* attS = (const float*)d_in[5];
    const float* attD = (const float*)d_in[6];
    const float* b2   = (const float*)d_in[7];
    const float* W3   = (const float*)d_in[8];
    const float* b3   = (const float*)d_in[9];
    float* out = (float*)d_out;

    const int T = 256;
    k_init  <<<(N_NODES + T - 1) / T, T>>>();
    k_edges <<<(E2 + T - 1) / T, T>>>(ei);
    k_scan  <<<1, SCAN_T>>>();
    k_fill  <<<(E2 + T - 1) / T, T>>>(ei);
    k_gemm1 <<<N_NODES / 16, T>>>(x, W1);
    k_gcn1  <<<(N_NODES * 32 + T - 1) / T, T>>>(b1);
    k_gemm2 <<<N_NODES / 16, T>>>(W2, attS, attD);
    k_maxred<<<(N_NODES + T - 1) / T, T>>>();
    k_gat   <<<(N_NODES + 7) / 8, T>>>(b2, W3);
    k_gcn2  <<<(N_NODES * 32 + T - 1) / T, T>>>(b3, out);
}

// round 6
// speedup vs baseline: 1.1068x; 1.0925x over previous
#include <cuda_runtime.h>
#include <cuda_fp16.h>
#include <math.h>

#define N_NODES 100000
#define E_EDGES 1600000
#define E2      (E_EDGES + N_NODES)   // 1,700,000 (edges + self loops)
#define IN_C    128
#define HID     64
#define HEADS   4
#define HH      (HEADS * HID)         // 256
#define OUT_C   2
#define NEG_SLOPE 0.2f
#define SCAN_T  1024

struct Edge { int src; float norm; };

// ---------------- scratch (static device globals) --------------------------
__device__ __align__(16) int    g_degi[N_NODES];
__device__ __align__(16) int    g_cnt[N_NODES];
__device__ __align__(16) int    g_rowptr[N_NODES + 1];
__device__ __align__(16) float  g_dinv[N_NODES];
__device__ __align__(16) Edge   g_csr[E2];
__device__ __align__(16) __half g_xw1h[(size_t)N_NODES * HID];   // fp16 staged
__device__ __align__(16) float  g_h0 [(size_t)N_NODES * HID];
__device__ __align__(16) __half g_xw2h[(size_t)N_NODES * HH];    // fp16 staged (51MB)
__device__ __align__(16) float  g_as [(size_t)N_NODES * HEADS];
__device__ __align__(16) float  g_ad [(size_t)N_NODES * HEADS];
__device__ __align__(16) float  g_mx[8];       // [0..3]=max a_s, [4..7]=max a_d
__device__ __align__(16) float  g_hw3[(size_t)N_NODES * OUT_C];

__device__ __forceinline__ float lrelu(float x) { return x > 0.0f ? x : NEG_SLOPE * x; }

__device__ __forceinline__ void atomicMaxFloat(float* addr, float value) {
    if (value >= 0.0f) atomicMax((int*)addr, __float_as_int(value));
    else               atomicMin((unsigned int*)addr, __float_as_uint(value));
}

// ---------------- CSR build -------------------------------------------------
__global__ void k_init() {
    int i = blockIdx.x * blockDim.x + threadIdx.x;
    if (i < N_NODES) { g_degi[i] = 0; g_cnt[i] = 0; }
    if (i < 8) g_mx[i] = -3.402823466e38f;
}

__global__ void k_edges(const int* __restrict__ ei) {
    int e = blockIdx.x * blockDim.x + threadIdx.x;
    if (e >= E2) return;
    int d = (e < E_EDGES) ? ei[E_EDGES + e] : (e - E_EDGES);
    atomicAdd(&g_degi[d], 1);
}

// single-block exclusive scan of degrees -> rowptr; also dinv
__global__ void k_scan() {
    __shared__ int part[SCAN_T];
    const int CH = (N_NODES + SCAN_T - 1) / SCAN_T;   // 98
    int t = threadIdx.x;
    int base = t * CH;
    int hi = min(base + CH, N_NODES);
    int sum = 0;
    for (int i = base; i < hi; i++) sum += g_degi[i];
    part[t] = sum;
    __syncthreads();
    for (int off = 1; off < SCAN_T; off <<= 1) {
        int v = (t >= off) ? part[t - off] : 0;
        __syncthreads();
        part[t] += v;
        __syncthreads();
    }
    int run = (t == 0) ? 0 : part[t - 1];
    for (int i = base; i < hi; i++) {
        g_rowptr[i] = run;
        int dg = g_degi[i];
        g_dinv[i] = dg > 0 ? rsqrtf((float)dg) : 0.0f;
        run += dg;
    }
    if (t == SCAN_T - 1) g_rowptr[N_NODES] = run;
}

__global__ void k_fill(const int* __restrict__ ei) {
    int e = blockIdx.x * blockDim.x + threadIdx.x;
    if (e >= E2) return;
    int s, d;
    if (e < E_EDGES) { s = ei[e]; d = ei[E_EDGES + e]; }
    else             { s = e - E_EDGES; d = s; }
    int pos = g_rowptr[d] + atomicAdd(&g_cnt[d], 1);
    Edge ed; ed.src = s; ed.norm = g_dinv[s] * g_dinv[d];
    g_csr[pos] = ed;                               // single 8B store
}

// ---------------- GEMM 1: xw1 = x @ W1  [N,128]x[128,64] -> fp16 -----------
__global__ void k_gemm1(const float* __restrict__ x, const float* __restrict__ W1) {
    __shared__ __align__(16) float As[16][IN_C + 4];
    __shared__ __align__(16) float Bs[IN_C][HID];
    int tid = threadIdx.x;                       // 256 threads
    for (int i = tid; i < IN_C * HID / 4; i += 256)
        ((float4*)&Bs[0][0])[i] = ((const float4*)W1)[i];
    int row0 = blockIdx.x * 16;
    for (int i = tid; i < 16 * IN_C / 4; i += 256) {
        int r = i / (IN_C / 4), k4 = i % (IN_C / 4);
        *(float4*)&As[r][k4 * 4] =
            *(const float4*)&x[(size_t)(row0 + r) * IN_C + k4 * 4];
    }
    __syncthreads();
    int r = tid >> 4, cg = tid & 15;             // 4 cols per thread
    float a0 = 0, a1 = 0, a2 = 0, a3 = 0;
    #pragma unroll 8
    for (int k = 0; k < IN_C; k++) {
        float a = As[r][k];
        float4 b = *(const float4*)&Bs[k][cg * 4];
        a0 += a * b.x; a1 += a * b.y; a2 += a * b.z; a3 += a * b.w;
    }
    __half2 h0 = __floats2half2_rn(a0, a1);
    __half2 h1 = __floats2half2_rn(a2, a3);
    uint2 u; u.x = *(unsigned*)&h0; u.y = *(unsigned*)&h1;
    *(uint2*)&g_xw1h[(size_t)(row0 + r) * HID + cg * 4] = u;
}

// ---------------- GCN-1 gather (fp16): h0[d]=relu(sum xw1[s]*norm + b1) ----
__global__ void k_gcn1(const float* __restrict__ b1) {
    int warp = (blockIdx.x * blockDim.x + threadIdx.x) >> 5;
    int lane = threadIdx.x & 31;
    if (warp >= N_NODES) return;
    int r0 = g_rowptr[warp], r1 = g_rowptr[warp + 1];
    float acc0 = 0.0f, acc1 = 0.0f;
    int off = lane * 2;
    int e = r0;
    for (; e + 4 <= r1; e += 4) {
        Edge e0 = g_csr[e], e1 = g_csr[e + 1], e2 = g_csr[e + 2], e3 = g_csr[e + 3];
        __half2 h0 = *(const __half2*)&g_xw1h[(size_t)e0.src * HID + off];
        __half2 h1 = *(const __half2*)&g_xw1h[(size_t)e1.src * HID + off];
        __half2 h2 = *(const __half2*)&g_xw1h[(size_t)e2.src * HID + off];
        __half2 h3 = *(const __half2*)&g_xw1h[(size_t)e3.src * HID + off];
        float2 v0 = __half22float2(h0), v1 = __half22float2(h1);
        float2 v2 = __half22float2(h2), v3 = __half22float2(h3);
        acc0 += v0.x * e0.norm + v1.x * e1.norm + v2.x * e2.norm + v3.x * e3.norm;
        acc1 += v0.y * e0.norm + v1.y * e1.norm + v2.y * e2.norm + v3.y * e3.norm;
    }
    for (; e < r1; e++) {
        Edge ed = g_csr[e];
        float2 v = __half22float2(*(const __half2*)&g_xw1h[(size_t)ed.src * HID + off]);
        acc0 += v.x * ed.norm; acc1 += v.y * ed.norm;
    }
    float2 o;
    o.x = fmaxf(acc0 + __ldg(&b1[off]),     0.0f);
    o.y = fmaxf(acc1 + __ldg(&b1[off + 1]), 0.0f);
    *(float2*)&g_h0[(size_t)warp * HID + off] = o;
}

// ---------------- GEMM 2: xw2 = h0 @ W2 -> fp16 (+ attention dots) ---------
__global__ void k_gemm2(const float* __restrict__ W2,
                        const float* __restrict__ attS,
                        const float* __restrict__ attD) {
    __shared__ __align__(16) float As[16][HID + 4];
    __shared__ __align__(16) float Bs[HID][128];
    __shared__ float aS[2][HID], aD[2][HID];
    int tid = threadIdx.x;                       // 256
    int row0 = blockIdx.x * 16;
    for (int i = tid; i < 16 * HID / 4; i += 256) {
        int r = i / (HID / 4), k4 = i % (HID / 4);
        *(float4*)&As[r][k4 * 4] =
            *(const float4*)&g_h0[(size_t)(row0 + r) * HID + k4 * 4];
    }
    int r = tid >> 4, cg = tid & 15;             // 8 cols per thread per half
    for (int half = 0; half < 2; half++) {
        __syncthreads();
        for (int i = tid; i < HID * 128 / 4; i += 256) {
            int k = i / 32, c4 = i % 32;
            *(float4*)&Bs[k][c4 * 4] =
                *(const float4*)&W2[(size_t)k * HH + half * 128 + c4 * 4];
        }
        if (tid < 128) {
            aS[tid >> 6][tid & 63] = attS[half * 128 + tid];
            aD[tid >> 6][tid & 63] = attD[half * 128 + tid];
        }
        __syncthreads();
        float acc[8];
        #pragma unroll
        for (int j = 0; j < 8; j++) acc[j] = 0.0f;
        #pragma unroll 8
        for (int k = 0; k < HID; k++) {
            float a = As[r][k];
            float4 b0 = *(const float4*)&Bs[k][cg * 8];
            float4 b1 = *(const float4*)&Bs[k][cg * 8 + 4];
            acc[0] += a * b0.x; acc[1] += a * b0.y; acc[2] += a * b0.z; acc[3] += a * b0.w;
            acc[4] += a * b1.x; acc[5] += a * b1.y; acc[6] += a * b1.z; acc[7] += a * b1.w;
        }
        int colbase = half * 128 + cg * 8;
        __half2 q0 = __floats2half2_rn(acc[0], acc[1]);
        __half2 q1 = __floats2half2_rn(acc[2], acc[3]);
        __half2 q2 = __floats2half2_rn(acc[4], acc[5]);
        __half2 q3 = __floats2half2_rn(acc[6], acc[7]);
        uint4 u;
        u.x = *(unsigned*)&q0; u.y = *(unsigned*)&q1;
        u.z = *(unsigned*)&q2; u.w = *(unsigned*)&q3;
        *(uint4*)&g_xw2h[(size_t)(row0 + r) * HH + colbase] = u;
        int hloc = cg >> 3;
        int off  = (cg & 7) * 8;
        float ps = 0.0f, pd = 0.0f;
        #pragma unroll
        for (int j = 0; j < 8; j++) {
            ps += acc[j] * aS[hloc][off + j];
            pd += acc[j] * aD[hloc][off + j];
        }
        #pragma unroll
        for (int o = 4; o >= 1; o >>= 1) {
            ps += __shfl_down_sync(0xffffffffu, ps, o);
            pd += __shfl_down_sync(0xffffffffu, pd, o);
        }
        if ((cg & 7) == 0) {
            int head = half * 2 + hloc;
            g_as[(size_t)(row0 + r) * HEADS + head] = ps;
            g_ad[(size_t)(row0 + r) * HEADS + head] = pd;
        }
    }
}

// ---------------- global per-head max of a_s / a_d -------------------------
__global__ void k_maxred() {
    int i = blockIdx.x * blockDim.x + threadIdx.x;
    int lane = threadIdx.x & 31;
    float4 a = make_float4(-3.4e38f, -3.4e38f, -3.4e38f, -3.4e38f);
    float4 d = a;
    if (i < N_NODES) {
        a = *(const float4*)&g_as[(size_t)i * HEADS];
        d = *(const float4*)&g_ad[(size_t)i * HEADS];
    }
    #pragma unroll
    for (int o = 16; o >= 1; o >>= 1) {
        a.x = fmaxf(a.x, __shfl_xor_sync(0xffffffffu, a.x, o));
        a.y = fmaxf(a.y, __shfl_xor_sync(0xffffffffu, a.y, o));
        a.z = fmaxf(a.z, __shfl_xor_sync(0xffffffffu, a.z, o));
        a.w = fmaxf(a.w, __shfl_xor_sync(0xffffffffu, a.w, o));
        d.x = fmaxf(d.x, __shfl_xor_sync(0xffffffffu, d.x, o));
        d.y = fmaxf(d.y, __shfl_xor_sync(0xffffffffu, d.y, o));
        d.z = fmaxf(d.z, __shfl_xor_sync(0xffffffffu, d.z, o));
        d.w = fmaxf(d.w, __shfl_xor_sync(0xffffffffu, d.w, o));
    }
    if (lane == 0) {
        atomicMaxFloat(&g_mx[0], a.x); atomicMaxFloat(&g_mx[1], a.y);
        atomicMaxFloat(&g_mx[2], a.z); atomicMaxFloat(&g_mx[3], a.w);
        atomicMaxFloat(&g_mx[4], d.x); atomicMaxFloat(&g_mx[5], d.y);
        atomicMaxFloat(&g_mx[6], d.z); atomicMaxFloat(&g_mx[7], d.w);
    }
}

// ---------------- fused GAT: single edge pass + bias + ELU + GEMM3 ---------
// Shift-invariant softmax with global per-head bound C_h (exact). fp16 gather.
__global__ void __launch_bounds__(256) k_gat(const float* __restrict__ b2,
                                             const float* __restrict__ W3) {
    __shared__ float sW3[HH * 2];
    __shared__ float sb2[HH];
    __shared__ float sC[HEADS];
    int tid = threadIdx.x;
    sW3[tid * 2]     = W3[tid * 2];
    sW3[tid * 2 + 1] = W3[tid * 2 + 1];
    sb2[tid]         = b2[tid];
    if (tid < HEADS) sC[tid] = lrelu(g_mx[tid] + g_mx[tid + 4]);
    __syncthreads();

    int warp = blockIdx.x * 8 + (tid >> 5);
    int lane = tid & 31;
    if (warp >= N_NODES) return;
    int r0 = g_rowptr[warp], r1 = g_rowptr[warp + 1];

    int head = lane >> 3;                        // 8 lanes per head
    int col  = lane * 8;                         // 8 fp16 channels per lane
    float adh = g_ad[(size_t)warp * HEADS + head];
    float Ch  = sC[head];

    float acc[8];
    #pragma unroll
    for (int j = 0; j < 8; j++) acc[j] = 0.0f;
    float den = 0.0f;

    int e = r0;
    for (; e + 4 <= r1; e += 4) {
        int s0 = g_csr[e].src,     s1 = g_csr[e + 1].src;
        int s2 = g_csr[e + 2].src, s3 = g_csr[e + 3].src;
        float as0 = g_as[(size_t)s0 * HEADS + head];
        float as1 = g_as[(size_t)s1 * HEADS + head];
        float as2 = g_as[(size_t)s2 * HEADS + head];
        float as3 = g_as[(size_t)s3 * HEADS + head];
        uint4 u0 = *(const uint4*)&g_xw2h[(size_t)s0 * HH + col];
        uint4 u1 = *(const uint4*)&g_xw2h[(size_t)s1 * HH + col];
        uint4 u2 = *(const uint4*)&g_xw2h[(size_t)s2 * HH + col];
        uint4 u3 = *(const uint4*)&g_xw2h[(size_t)s3 * HH + col];
        float w0 = __expf(lrelu(as0 + adh) - Ch);
        float w1 = __expf(lrelu(as1 + adh) - Ch);
        float w2 = __expf(lrelu(as2 + adh) - Ch);
        float w3 = __expf(lrelu(as3 + adh) - Ch);
        den += (w0 + w1) + (w2 + w3);
        {
            float2 f0 = __half22float2(*(__half2*)&u0.x);
            float2 f1 = __half22float2(*(__half2*)&u0.y);
            float2 f2 = __half22float2(*(__half2*)&u0.z);
            float2 f3 = __half22float2(*(__half2*)&u0.w);
            acc[0] += f0.x * w0; acc[1] += f0.y * w0;
            acc[2] += f1.x * w0; acc[3] += f1.y * w0;
            acc[4] += f2.x * w0; acc[5] += f2.y * w0;
            acc[6] += f3.x * w0; acc[7] += f3.y * w0;
        }
        {
            float2 f0 = __half22float2(*(__half2*)&u1.x);
            float2 f1 = __half22float2(*(__half2*)&u1.y);
            float2 f2 = __half22float2(*(__half2*)&u1.z);
            float2 f3 = __half22float2(*(__half2*)&u1.w);
            acc[0] += f0.x * w1; acc[1] += f0.y * w1;
            acc[2] += f1.x * w1; acc[3] += f1.y * w1;
            acc[4] += f2.x * w1; acc[5] += f2.y * w1;
            acc[6] += f3.x * w1; acc[7] += f3.y * w1;
        }
        {
            float2 f0 = __half22float2(*(__half2*)&u2.x);
            float2 f1 = __half22float2(*(__half2*)&u2.y);
            float2 f2 = __half22float2(*(__half2*)&u2.z);
            float2 f3 = __half22float2(*(__half2*)&u2.w);
            acc[0] += f0.x * w2; acc[1] += f0.y * w2;
            acc[2] += f1.x * w2; acc[3] += f1.y * w2;
            acc[4] += f2.x * w2; acc[5] += f2.y * w2;
            acc[6] += f3.x * w2; acc[7] += f3.y * w2;
        }
        {
            float2 f0 = __half22float2(*(__half2*)&u3.x);
            float2 f1 = __half22float2(*(__half2*)&u3.y);
            float2 f2 = __half22float2(*(__half2*)&u3.z);
            float2 f3 = __half22float2(*(__half2*)&u3.w);
            acc[0] += f0.x * w3; acc[1] += f0.y * w3;
            acc[2] += f1.x * w3; acc[3] += f1.y * w3;
            acc[4] += f2.x * w3; acc[5] += f2.y * w3;
            acc[6] += f3.x * w3; acc[7] += f3.y * w3;
        }
    }
    for (; e < r1; e++) {
        int s = g_csr[e].src;
        float ash = g_as[(size_t)s * HEADS + head];
        float w = __expf(lrelu(ash + adh) - Ch);
        den += w;
        uint4 u = *(const uint4*)&g_xw2h[(size_t)s * HH + col];
        float2 f0 = __half22float2(*(__half2*)&u.x);
        float2 f1 = __half22float2(*(__half2*)&u.y);
        float2 f2 = __half22float2(*(__half2*)&u.z);
        float2 f3 = __half22float2(*(__half2*)&u.w);
        acc[0] += f0.x * w; acc[1] += f0.y * w;
        acc[2] += f1.x * w; acc[3] += f1.y * w;
        acc[4] += f2.x * w; acc[5] += f2.y * w;
        acc[6] += f3.x * w; acc[7] += f3.y * w;
    }
    float inv = 1.0f / den;                      // den>0 (self-loop)

    // epilogue: normalize, +b2, ELU, dot with W3 columns (fused gemm3)
    float a0 = 0.0f, a1 = 0.0f;
    #pragma unroll
    for (int j = 0; j < 8; j++) {
        int c = col + j;
        float v = acc[j] * inv + sb2[c];
        v = v > 0.0f ? v : expm1f(v);
        a0 += v * sW3[c * 2];
        a1 += v * sW3[c * 2 + 1];
    }
    #pragma unroll
    for (int o = 16; o >= 1; o >>= 1) {
        a0 += __shfl_xor_sync(0xffffffffu, a0, o);
        a1 += __shfl_xor_sync(0xffffffffu, a1, o);
    }
    if (lane == 0) {
        g_hw3[(size_t)warp * 2]     = a0;
        g_hw3[(size_t)warp * 2 + 1] = a1;
    }
}

// ---------------- GCN-2 gather: out[d] = sum hw3[s]*norm + b3 --------------
__global__ void k_gcn2(const float* __restrict__ b3, float* __restrict__ out) {
    int warp = (blockIdx.x * blockDim.x + threadIdx.x) >> 5;
    int lane = threadIdx.x & 31;
    if (warp >= N_NODES) return;
    int r0 = g_rowptr[warp], r1 = g_rowptr[warp + 1];
    float acc0 = 0.0f, acc1 = 0.0f;
    for (int e = r0 + lane; e < r1; e += 32) {
        Edge ed = g_csr[e];
        float2 v = *(const float2*)&g_hw3[(size_t)ed.src * 2];
        acc0 += v.x * ed.norm; acc1 += v.y * ed.norm;
    }
    #pragma unroll
    for (int o = 16; o >= 1; o >>= 1) {
        acc0 += __shfl_xor_sync(0xffffffffu, acc0, o);
        acc1 += __shfl_xor_sync(0xffffffffu, acc1, o);
    }
    if (lane == 0) {
        out[(size_t)warp * 2]     = acc0 + __ldg(&b3[0]);
        out[(size_t)warp * 2 + 1] = acc1 + __ldg(&b3[1]);
    }
}

// ---------------- launch -----------------------------------------------------
extern "C" void kernel_launch(void* const* d_in, const int* in_sizes, int n_in,
                              void* d_out, int out_size) {
    const float* x    = (const float*)d_in[0];
    const int*   ei   = (const int*)d_in[1];      // int32
    const float* W1   = (const float*)d_in[2];
    const float* b1   = (const float*)d_in[3];
    const float* W2   = (const float*)d_in[4];
    const float* attS = (const float*)d_in[5];
    const float* attD = (const float*)d_in[6];
    const float* b2   = (const float*)d_in[7];
    const float* W3   = (const float*)d_in[8];
    const float* b3   = (const float*)d_in[9];
    float* out = (float*)d_out;

    const int T = 256;
    k_init  <<<(N_NODES + T - 1) / T, T>>>();
    k_edges <<<(E2 + T - 1) / T, T>>>(ei);
    k_scan  <<<1, SCAN_T>>>();
    k_fill  <<<(E2 + T - 1) / T, T>>>(ei);
    k_gemm1 <<<N_NODES / 16, T>>>(x, W1);
    k_gcn1  <<<(N_NODES * 32 + T - 1) / T, T>>>(b1);
    k_gemm2 <<<N_NODES / 16, T>>>(W2, attS, attD);
    k_maxred<<<(N_NODES + T - 1) / T, T>>>();
    k_gat   <<<(N_NODES + 7) / 8, T>>>(b2, W3);
    k_gcn2  <<<(N_NODES * 32 + T - 1) / T, T>>>(b3, out);
}

// round 7
// speedup vs baseline: 1.6910x; 1.5278x over previous
#include <cuda_runtime.h>
#include <cuda_fp16.h>
#include <math.h>

#define N_NODES 100000
#define E_EDGES 1600000
#define E2      (E_EDGES + N_NODES)   // 1,700,000
#define IN_C    128
#define HID     64
#define HEADS   4
#define HH      (HEADS * HID)         // 256
#define OUT_C   2
#define NEG_SLOPE 0.2f
#define SCAN_T  1024

struct Edge { int src; float norm; };

// ---------------- scratch ----------------------------------------------------
__device__ __align__(16) int    g_degi[N_NODES];
__device__ __align__(16) int    g_cnt[N_NODES];
__device__ __align__(16) int    g_rowptr[N_NODES + 1];
__device__ __align__(16) float  g_dinv[N_NODES];
__device__ __align__(16) Edge   g_csr[E2];
__device__ __align__(16) __half g_xw1h[(size_t)N_NODES * HID];
__device__ __align__(16) float  g_h0 [(size_t)N_NODES * HID];
__device__ __align__(16) __half g_xw2h[(size_t)N_NODES * HH];    // 51MB, L2-resident
__device__ __align__(16) float  g_as [(size_t)N_NODES * HEADS];
__device__ __align__(16) float  g_ad [(size_t)N_NODES * HEADS];
__device__ __align__(16) float  g_mx[8];
__device__ __align__(16) float  g_hw3[(size_t)N_NODES * OUT_C];

__device__ __forceinline__ float lrelu(float x) { return x > 0.0f ? x : NEG_SLOPE * x; }

__device__ __forceinline__ void atomicMaxFloat(float* addr, float value) {
    if (value >= 0.0f) atomicMax((int*)addr, __float_as_int(value));
    else               atomicMin((unsigned int*)addr, __float_as_uint(value));
}

// ---------------- CSR build --------------------------------------------------
__global__ void k_init() {
    int i = blockIdx.x * blockDim.x + threadIdx.x;
    if (i < N_NODES) { g_degi[i] = 0; g_cnt[i] = 0; }
    if (i < 8) g_mx[i] = -3.402823466e38f;
}

__global__ void k_edges(const int* __restrict__ ei) {
    int e = blockIdx.x * blockDim.x + threadIdx.x;
    if (e >= E2) return;
    int d = (e < E_EDGES) ? ei[E_EDGES + e] : (e - E_EDGES);
    atomicAdd(&g_degi[d], 1);
}

__global__ void k_scan() {
    __shared__ int part[SCAN_T];
    const int CH = (N_NODES + SCAN_T - 1) / SCAN_T;
    int t = threadIdx.x;
    int base = t * CH;
    int hi = min(base + CH, N_NODES);
    int sum = 0;
    for (int i = base; i < hi; i++) sum += g_degi[i];
    part[t] = sum;
    __syncthreads();
    for (int off = 1; off < SCAN_T; off <<= 1) {
        int v = (t >= off) ? part[t - off] : 0;
        __syncthreads();
        part[t] += v;
        __syncthreads();
    }
    int run = (t == 0) ? 0 : part[t - 1];
    for (int i = base; i < hi; i++) {
        g_rowptr[i] = run;
        int dg = g_degi[i];
        g_dinv[i] = dg > 0 ? rsqrtf((float)dg) : 0.0f;
        run += dg;
    }
    if (t == SCAN_T - 1) g_rowptr[N_NODES] = run;
}

__global__ void k_fill(const int* __restrict__ ei) {
    int e = blockIdx.x * blockDim.x + threadIdx.x;
    if (e >= E2) return;
    int s, d;
    if (e < E_EDGES) { s = ei[e]; d = ei[E_EDGES + e]; }
    else             { s = e - E_EDGES; d = s; }
    int pos = g_rowptr[d] + atomicAdd(&g_cnt[d], 1);
    Edge ed; ed.src = s; ed.norm = g_dinv[s] * g_dinv[d];
    g_csr[pos] = ed;
}

// ---------------- GEMM 1: xw1h = fp16(x @ W1)   64x64 tile, 4x4/thread -----
__global__ void __launch_bounds__(256) k_gemm1(const float* __restrict__ x,
                                               const float* __restrict__ W1) {
    __shared__ __align__(16) float As[64][68];   // 64 rows x 64 k (chunk)
    __shared__ __align__(16) float Bs[64][HID];  // 64 k x 64 cols
    int tid = threadIdx.x;
    int tx = tid & 15, ty = tid >> 4;            // 16x16 thread grid
    int row0 = blockIdx.x * 64;
    float acc[4][4];
    #pragma unroll
    for (int i = 0; i < 4; i++)
        #pragma unroll
        for (int j = 0; j < 4; j++) acc[i][j] = 0.0f;

    for (int kc = 0; kc < IN_C; kc += 64) {
        __syncthreads();
        // load A chunk: 64 rows x 64 k  (1024 float4, 4 per thread)
        #pragma unroll
        for (int it = 0; it < 4; it++) {
            int idx = tid + it * 256;            // float4 index
            int r = idx >> 4, k4 = idx & 15;
            int row = row0 + r;
            float4 v = make_float4(0.f, 0.f, 0.f, 0.f);
            if (row < N_NODES)
                v = *(const float4*)&x[(size_t)row * IN_C + kc + k4 * 4];
            *(float4*)&As[r][k4 * 4] = v;
        }
        // load B chunk: 64 k x 64 cols (1024 float4, 4 per thread)
        #pragma unroll
        for (int it = 0; it < 4; it++) {
            int idx = tid + it * 256;
            int k = idx >> 4, c4 = idx & 15;
            *(float4*)&Bs[k][c4 * 4] = *(const float4*)&W1[(size_t)(kc + k) * HID + c4 * 4];
        }
        __syncthreads();
        #pragma unroll 16
        for (int k = 0; k < 64; k++) {
            float a0 = As[ty * 4 + 0][k], a1 = As[ty * 4 + 1][k];
            float a2 = As[ty * 4 + 2][k], a3 = As[ty * 4 + 3][k];
            float4 b = *(const float4*)&Bs[k][tx * 4];
            acc[0][0] += a0 * b.x; acc[0][1] += a0 * b.y; acc[0][2] += a0 * b.z; acc[0][3] += a0 * b.w;
            acc[1][0] += a1 * b.x; acc[1][1] += a1 * b.y; acc[1][2] += a1 * b.z; acc[1][3] += a1 * b.w;
            acc[2][0] += a2 * b.x; acc[2][1] += a2 * b.y; acc[2][2] += a2 * b.z; acc[2][3] += a2 * b.w;
            acc[3][0] += a3 * b.x; acc[3][1] += a3 * b.y; acc[3][2] += a3 * b.z; acc[3][3] += a3 * b.w;
        }
    }
    #pragma unroll
    for (int i = 0; i < 4; i++) {
        int row = row0 + ty * 4 + i;
        if (row < N_NODES) {
            __half2 p0 = __floats2half2_rn(acc[i][0], acc[i][1]);
            __half2 p1 = __floats2half2_rn(acc[i][2], acc[i][3]);
            uint2 u; u.x = *(unsigned*)&p0; u.y = *(unsigned*)&p1;
            *(uint2*)&g_xw1h[(size_t)row * HID + tx * 4] = u;
        }
    }
}

// ---------------- GCN-1 gather (fp16, 8-unroll) ----------------------------
__global__ void k_gcn1(const float* __restrict__ b1) {
    int warp = (blockIdx.x * blockDim.x + threadIdx.x) >> 5;
    int lane = threadIdx.x & 31;
    if (warp >= N_NODES) return;
    int r0 = g_rowptr[warp], r1 = g_rowptr[warp + 1];
    float acc0 = 0.0f, acc1 = 0.0f;
    int off = lane * 2;
    int e = r0;
    for (; e + 8 <= r1; e += 8) {
        Edge ed[8];
        #pragma unroll
        for (int j = 0; j < 8; j++) ed[j] = g_csr[e + j];
        __half2 hv[8];
        #pragma unroll
        for (int j = 0; j < 8; j++)
            hv[j] = *(const __half2*)&g_xw1h[(size_t)ed[j].src * HID + off];
        #pragma unroll
        for (int j = 0; j < 8; j++) {
            float2 v = __half22float2(hv[j]);
            acc0 += v.x * ed[j].norm; acc1 += v.y * ed[j].norm;
        }
    }
    for (; e < r1; e++) {
        Edge ed = g_csr[e];
        float2 v = __half22float2(*(const __half2*)&g_xw1h[(size_t)ed.src * HID + off]);
        acc0 += v.x * ed.norm; acc1 += v.y * ed.norm;
    }
    float2 o;
    o.x = fmaxf(acc0 + __ldg(&b1[off]),     0.0f);
    o.y = fmaxf(acc1 + __ldg(&b1[off + 1]), 0.0f);
    *(float2*)&g_h0[(size_t)warp * HID + off] = o;
}

// ---------------- GEMM 2: xw2h = fp16(h0 @ W2), + attention dots -----------
// grid (rowBlocks, 4): blockIdx.y = head (64-col chunk). 64x64 tile, 4x4/thread.
__global__ void __launch_bounds__(256) k_gemm2(const float* __restrict__ W2,
                                               const float* __restrict__ attS,
                                               const float* __restrict__ attD) {
    __shared__ __align__(16) float As[64][68];   // 64 rows x 64 k
    __shared__ __align__(16) float Bs[64][64];   // 64 k x 64 cols
    __shared__ float sa[64], sd[64];
    int tid = threadIdx.x;
    int tx = tid & 15, ty = tid >> 4;
    int head = blockIdx.y;
    int row0 = blockIdx.x * 64;

    // load A (h0): 64 rows x 64 k
    #pragma unroll
    for (int it = 0; it < 4; it++) {
        int idx = tid + it * 256;
        int r = idx >> 4, k4 = idx & 15;
        int row = row0 + r;
        float4 v = make_float4(0.f, 0.f, 0.f, 0.f);
        if (row < N_NODES)
            v = *(const float4*)&g_h0[(size_t)row * HID + k4 * 4];
        *(float4*)&As[r][k4 * 4] = v;
    }
    // load B: W2[k][head*64 + c]
    #pragma unroll
    for (int it = 0; it < 4; it++) {
        int idx = tid + it * 256;
        int k = idx >> 4, c4 = idx & 15;
        *(float4*)&Bs[k][c4 * 4] =
            *(const float4*)&W2[(size_t)k * HH + head * 64 + c4 * 4];
    }
    if (tid < 64) { sa[tid] = attS[head * 64 + tid]; sd[tid] = attD[head * 64 + tid]; }
    __syncthreads();

    float acc[4][4];
    #pragma unroll
    for (int i = 0; i < 4; i++)
        #pragma unroll
        for (int j = 0; j < 4; j++) acc[i][j] = 0.0f;

    #pragma unroll 16
    for (int k = 0; k < 64; k++) {
        float a0 = As[ty * 4 + 0][k], a1 = As[ty * 4 + 1][k];
        float a2 = As[ty * 4 + 2][k], a3 = As[ty * 4 + 3][k];
        float4 b = *(const float4*)&Bs[k][tx * 4];
        acc[0][0] += a0 * b.x; acc[0][1] += a0 * b.y; acc[0][2] += a0 * b.z; acc[0][3] += a0 * b.w;
        acc[1][0] += a1 * b.x; acc[1][1] += a1 * b.y; acc[1][2] += a1 * b.z; acc[1][3] += a1 * b.w;
        acc[2][0] += a2 * b.x; acc[2][1] += a2 * b.y; acc[2][2] += a2 * b.z; acc[2][3] += a2 * b.w;
        acc[3][0] += a3 * b.x; acc[3][1] += a3 * b.y; acc[3][2] += a3 * b.z; acc[3][3] += a3 * b.w;
    }

    // store fp16 tile
    #pragma unroll
    for (int i = 0; i < 4; i++) {
        int row = row0 + ty * 4 + i;
        if (row < N_NODES) {
            __half2 p0 = __floats2half2_rn(acc[i][0], acc[i][1]);
            __half2 p1 = __floats2half2_rn(acc[i][2], acc[i][3]);
            uint2 u; u.x = *(unsigned*)&p0; u.y = *(unsigned*)&p1;
            *(uint2*)&g_xw2h[(size_t)row * HH + head * 64 + tx * 4] = u;
        }
    }

    // attention dots: reduce 4-col partials across the 16 tx lanes
    float ps[4], pd[4];
    #pragma unroll
    for (int i = 0; i < 4; i++) {
        float s = 0.f, d = 0.f;
        #pragma unroll
        for (int j = 0; j < 4; j++) {
            s += acc[i][j] * sa[tx * 4 + j];
            d += acc[i][j] * sd[tx * 4 + j];
        }
        ps[i] = s; pd[i] = d;
    }
    #pragma unroll
    for (int off = 8; off >= 1; off >>= 1) {
        #pragma unroll
        for (int i = 0; i < 4; i++) {
            ps[i] += __shfl_xor_sync(0xffffffffu, ps[i], off);
            pd[i] += __shfl_xor_sync(0xffffffffu, pd[i], off);
        }
    }
    if (tx == 0) {
        #pragma unroll
        for (int i = 0; i < 4; i++) {
            int row = row0 + ty * 4 + i;
            if (row < N_NODES) {
                g_as[(size_t)row * HEADS + head] = ps[i];
                g_ad[(size_t)row * HEADS + head] = pd[i];
            }
        }
    }
}

// ---------------- global per-head max of a_s / a_d -------------------------
__global__ void k_maxred() {
    int i = blockIdx.x * blockDim.x + threadIdx.x;
    int lane = threadIdx.x & 31;
    float4 a = make_float4(-3.4e38f, -3.4e38f, -3.4e38f, -3.4e38f);
    float4 d = a;
    if (i < N_NODES) {
        a = *(const float4*)&g_as[(size_t)i * HEADS];
        d = *(const float4*)&g_ad[(size_t)i * HEADS];
    }
    #pragma unroll
    for (int o = 16; o >= 1; o >>= 1) {
        a.x = fmaxf(a.x, __shfl_xor_sync(0xffffffffu, a.x, o));
        a.y = fmaxf(a.y, __shfl_xor_sync(0xffffffffu, a.y, o));
        a.z = fmaxf(a.z, __shfl_xor_sync(0xffffffffu, a.z, o));
        a.w = fmaxf(a.w, __shfl_xor_sync(0xffffffffu, a.w, o));
        d.x = fmaxf(d.x, __shfl_xor_sync(0xffffffffu, d.x, o));
        d.y = fmaxf(d.y, __shfl_xor_sync(0xffffffffu, d.y, o));
        d.z = fmaxf(d.z, __shfl_xor_sync(0xffffffffu, d.z, o));
        d.w = fmaxf(d.w, __shfl_xor_sync(0xffffffffu, d.w, o));
    }
    if (lane == 0) {
        atomicMaxFloat(&g_mx[0], a.x); atomicMaxFloat(&g_mx[1], a.y);
        atomicMaxFloat(&g_mx[2], a.z); atomicMaxFloat(&g_mx[3], a.w);
        atomicMaxFloat(&g_mx[4], d.x); atomicMaxFloat(&g_mx[5], d.y);
        atomicMaxFloat(&g_mx[6], d.z); atomicMaxFloat(&g_mx[7], d.w);
    }
}

// ---------------- fused GAT: 2 warps per node, fp16 gather -----------------
// block = 256 threads = 8 warps = 4 nodes (grid 25000 exactly covers 100000)
__global__ void __launch_bounds__(256) k_gat(const float* __restrict__ b2,
                                             const float* __restrict__ W3) {
    __shared__ float sW3[HH * 2];
    __shared__ float sb2[HH];
    __shared__ float sC[HEADS];
    __shared__ float sPart[8][2];
    int tid = threadIdx.x;
    sW3[tid * 2]     = W3[tid * 2];
    sW3[tid * 2 + 1] = W3[tid * 2 + 1];
    sb2[tid]         = b2[tid];
    if (tid < HEADS) sC[tid] = lrelu(g_mx[tid] + g_mx[tid + 4]);
    __syncthreads();

    int wlocal = tid >> 5;                       // 0..7
    int node   = blockIdx.x * 4 + (wlocal >> 1);
    int hpart  = wlocal & 1;                     // which 128-channel half
    int lane   = tid & 31;
    int r0 = g_rowptr[node], r1 = g_rowptr[node + 1];

    int col  = hpart * 128 + lane * 4;           // 4 fp16 channels per lane
    int head = col >> 6;
    float adh = g_ad[(size_t)node * HEADS + head];
    float Ch  = sC[head];

    float acc[4];
    #pragma unroll
    for (int j = 0; j < 4; j++) acc[j] = 0.0f;
    float den = 0.0f;

    int e = r0;
    for (; e + 4 <= r1; e += 4) {
        int s0 = g_csr[e].src,     s1 = g_csr[e + 1].src;
        int s2 = g_csr[e + 2].src, s3 = g_csr[e + 3].src;
        float as0 = g_as[(size_t)s0 * HEADS + head];
        float as1 = g_as[(size_t)s1 * HEADS + head];
        float as2 = g_as[(size_t)s2 * HEADS + head];
        float as3 = g_as[(size_t)s3 * HEADS + head];
        uint2 u0 = *(const uint2*)&g_xw2h[(size_t)s0 * HH + col];
        uint2 u1 = *(const uint2*)&g_xw2h[(size_t)s1 * HH + col];
        uint2 u2 = *(const uint2*)&g_xw2h[(size_t)s2 * HH + col];
        uint2 u3 = *(const uint2*)&g_xw2h[(size_t)s3 * HH + col];
        float w0 = __expf(lrelu(as0 + adh) - Ch);
        float w1 = __expf(lrelu(as1 + adh) - Ch);
        float w2 = __expf(lrelu(as2 + adh) - Ch);
        float w3 = __expf(lrelu(as3 + adh) - Ch);
        den += (w0 + w1) + (w2 + w3);
        float2 f;
        f = __half22float2(*(__half2*)&u0.x); acc[0] += f.x * w0; acc[1] += f.y * w0;
        f = __half22float2(*(__half2*)&u0.y); acc[2] += f.x * w0; acc[3] += f.y * w0;
        f = __half22float2(*(__half2*)&u1.x); acc[0] += f.x * w1; acc[1] += f.y * w1;
        f = __half22float2(*(__half2*)&u1.y); acc[2] += f.x * w1; acc[3] += f.y * w1;
        f = __half22float2(*(__half2*)&u2.x); acc[0] += f.x * w2; acc[1] += f.y * w2;
        f = __half22float2(*(__half2*)&u2.y); acc[2] += f.x * w2; acc[3] += f.y * w2;
        f = __half22float2(*(__half2*)&u3.x); acc[0] += f.x * w3; acc[1] += f.y * w3;
        f = __half22float2(*(__half2*)&u3.y); acc[2] += f.x * w3; acc[3] += f.y * w3;
    }
    for (; e < r1; e++) {
        int s = g_csr[e].src;
        float ash = g_as[(size_t)s * HEADS + head];
        float w = __expf(lrelu(ash + adh) - Ch);
        den += w;
        uint2 u = *(const uint2*)&g_xw2h[(size_t)s * HH + col];
        float2 f;
        f = __half22float2(*(__half2*)&u.x); acc[0] += f.x * w; acc[1] += f.y * w;
        f = __half22float2(*(__half2*)&u.y); acc[2] += f.x * w; acc[3] += f.y * w;
    }
    float inv = 1.0f / den;

    float a0 = 0.0f, a1 = 0.0f;
    #pragma unroll
    for (int j = 0; j < 4; j++) {
        int c = col + j;
        float v = acc[j] * inv + sb2[c];
        v = v > 0.0f ? v : expm1f(v);
        a0 += v * sW3[c * 2];
        a1 += v * sW3[c * 2 + 1];
    }
    #pragma unroll
    for (int o = 16; o >= 1; o >>= 1) {
        a0 += __shfl_xor_sync(0xffffffffu, a0, o);
        a1 += __shfl_xor_sync(0xffffffffu, a1, o);
    }
    if (lane == 0) { sPart[wlocal][0] = a0; sPart[wlocal][1] = a1; }
    __syncthreads();
    if (tid < 4) {
        int n = blockIdx.x * 4 + tid;
        g_hw3[(size_t)n * 2]     = sPart[tid * 2][0] + sPart[tid * 2 + 1][0];
        g_hw3[(size_t)n * 2 + 1] = sPart[tid * 2][1] + sPart[tid * 2 + 1][1];
    }
}

// ---------------- GCN-2 gather ----------------------------------------------
__global__ void k_gcn2(const float* __restrict__ b3, float* __restrict__ out) {
    int warp = (blockIdx.x * blockDim.x + threadIdx.x) >> 5;
    int lane = threadIdx.x & 31;
    if (warp >= N_NODES) return;
    int r0 = g_rowptr[warp], r1 = g_rowptr[warp + 1];
    float acc0 = 0.0f, acc1 = 0.0f;
    for (int e = r0 + lane; e < r1; e += 32) {
        Edge ed = g_csr[e];
        float2 v = *(const float2*)&g_hw3[(size_t)ed.src * 2];
        acc0 += v.x * ed.norm; acc1 += v.y * ed.norm;
    }
    #pragma unroll
    for (int o = 16; o >= 1; o >>= 1) {
        acc0 += __shfl_xor_sync(0xffffffffu, acc0, o);
        acc1 += __shfl_xor_sync(0xffffffffu, acc1, o);
    }
    if (lane == 0) {
        out[(size_t)warp * 2]     = acc0 + __ldg(&b3[0]);
        out[(size_t)warp * 2 + 1] = acc1 + __ldg(&b3[1]);
    }
}

// ---------------- launch -------------------------------------------------------
extern "C" void kernel_launch(void* const* d_in, const int* in_sizes, int n_in,
                              void* d_out, int out_size) {
    const float* x    = (const float*)d_in[0];
    const int*   ei   = (const int*)d_in[1];
    const float* W1   = (const float*)d_in[2];
    const float* b1   = (const float*)d_in[3];
    const float* W2   = (const float*)d_in[4];
    const float* attS = (const float*)d_in[5];
    const float* attD = (const float*)d_in[6];
    const float* b2   = (const float*)d_in[7];
    const float* W3   = (const float*)d_in[8];
    const float* b3   = (const float*)d_in[9];
    float* out = (float*)d_out;

    const int T = 256;
    const int RB = (N_NODES + 63) / 64;          // 1563 row blocks
    k_init  <<<(N_NODES + T - 1) / T, T>>>();
    k_edges <<<(E2 + T - 1) / T, T>>>(ei);
    k_scan  <<<1, SCAN_T>>>();
    k_fill  <<<(E2 + T - 1) / T, T>>>(ei);
    k_gemm1 <<<RB, T>>>(x, W1);
    k_gcn1  <<<(N_NODES * 32 + T - 1) / T, T>>>(b1);
    k_gemm2 <<<dim3(RB, HEADS), T>>>(W2, attS, attD);
    k_maxred<<<(N_NODES + T - 1) / T, T>>>();
    k_gat   <<<N_NODES / 4, T>>>(b2, W3);
    k_gcn2  <<<(N_NODES * 32 + T - 1) / T, T>>>(b3, out);
}